// round 16
// baseline (speedup 1.0000x reference)
#include <cuda_runtime.h>
#include <math.h>

#define BB 16
#define AA 8732
#define CC 91
#define NC 90
#define KK 400
#define KK2 416          /* padded to 13 full warps */
#define NWRD 13
#define NCAND (NC*KK)
#define DD 200
#define MKEY_N (NC*200)  /* 18000 merge keys per image */
#define IMGV 300.0f
#define OFFV 302.0f
#define THRESH 0.01f
#define NMSV 0.45f
#define NEGINF (-1e30f)
#define CLIPV 4.135166556742356f

// ---------------- scratch (device globals; no allocation) ----------------
__device__ float  g_probsT[(size_t)BB*CC*AA];
__device__ float4 g_boxes[BB*AA];
__device__ float  g_candVal[BB*NCAND];
__device__ int    g_candIdx[BB*NCAND];
__device__ float4 g_candBox[BB*NCAND];
__device__ float  g_survVal[(size_t)BB*NC*KK];
__device__ int    g_survK[(size_t)BB*NC*KK];
__device__ int    g_survCnt[BB*NC];
__device__ int    g_keepFlat[BB*DD];

// ---------------- kernel 1: softmax (class-split x2) + fused box decode ----------------
__global__ void softmax_kernel(const float* __restrict__ logits,
                               const float* __restrict__ rel,
                               const float* __restrict__ anchors) {
    __shared__ float s[CC * 129];
    const unsigned FULL = 0xFFFFFFFFu;
    int b = blockIdx.y;
    int a0 = blockIdx.x * 128;
    int na = AA - a0; if (na > 128) na = 128;
    int tid = threadIdx.x;
    int al   = tid >> 1;
    int half = tid & 1;

    if (tid < na) {
        int a = a0 + tid;
        int i = b*AA + a;
        float4 an = ((const float4*)anchors)[a];
        float4 rg = ((const float4*)rel)[i];
        float wa  = __fsub_rn(an.z, an.x);
        float ha  = __fsub_rn(an.w, an.y);
        float cxa = __fadd_rn(an.x, __fmul_rn(0.5f, wa));
        float cya = __fadd_rn(an.y, __fmul_rn(0.5f, ha));
        float dx  = __fdiv_rn(rg.x, 10.0f);
        float dy  = __fdiv_rn(rg.y, 10.0f);
        float dw  = fminf(__fdiv_rn(rg.z, 5.0f), CLIPV);
        float dh  = fminf(__fdiv_rn(rg.w, 5.0f), CLIPV);
        float cx  = __fadd_rn(__fmul_rn(dx, wa), cxa);
        float cy  = __fadd_rn(__fmul_rn(dy, ha), cya);
        float w   = __fmul_rn(expf(dw), wa);
        float h   = __fmul_rn(expf(dh), ha);
        float4 o;
        o.x = fminf(fmaxf(__fsub_rn(cx, __fmul_rn(0.5f, w)), 0.0f), IMGV);
        o.y = fminf(fmaxf(__fsub_rn(cy, __fmul_rn(0.5f, h)), 0.0f), IMGV);
        o.z = fminf(fmaxf(__fadd_rn(cx, __fmul_rn(0.5f, w)), 0.0f), IMGV);
        o.w = fminf(fmaxf(__fadd_rn(cy, __fmul_rn(0.5f, h)), 0.0f), IMGV);
        g_boxes[i] = o;
    }

    const float* base = logits + (size_t)(b*AA + a0) * CC;
    for (int idx = tid; idx < na * CC; idx += 256) {
        int a2 = idx / CC;
        int c  = idx - a2 * CC;
        s[c * 129 + a2] = base[idx];
    }
    __syncthreads();

    {   // ALL threads execute (shfl stays warp-uniform)
        int c_beg = half ? 46 : 0;
        int c_end = half ? CC : 46;
        float m = NEGINF;
        for (int c = c_beg; c < c_end; c++) m = fmaxf(m, s[c*129 + al]);
        float mo = __shfl_xor_sync(FULL, m, 1);
        m = fmaxf(m, mo);
        float sum = 0.0f;
        for (int c = c_beg; c < c_end; c++) {
            float e = expf(__fsub_rn(s[c*129 + al], m));
            s[c*129 + al] = e;
            sum = __fadd_rn(sum, e);
        }
        float so = __shfl_xor_sync(FULL, sum, 1);
        float s0 = half ? so : sum;
        float s1 = half ? sum : so;
        float tot = __fadd_rn(s0, s1);
        float rs = __frcp_rn(tot);
        for (int c = c_beg; c < c_end; c++)
            s[c*129 + al] = __fmul_rn(s[c*129 + al], rs);
    }
    __syncthreads();

    for (int idx = tid; idx < CC*128; idx += 256) {
        int c = idx >> 7;
        int a = idx & 127;
        if (a < na)
            g_probsT[((size_t)(b*CC + c))*AA + a0 + a] = s[c*129 + a];
    }
}

// ---------------- kernel 2: per-(b,class) top-400, 512 threads ----------------
__global__ void __launch_bounds__(512) topk_kernel() {
    __shared__ unsigned keys[AA];
    __shared__ unsigned long long sel[512];
    __shared__ int hist[256];
    __shared__ int s_c5[5];
    __shared__ unsigned s_prefix, s_pmask;
    __shared__ int s_need, s_nsel, s_neq;
    const unsigned FULL = 0xFFFFFFFFu;
    int crow = blockIdx.x;   // class-1
    int b    = blockIdx.y;
    int tid  = threadIdx.x;
    int lane = tid & 31;
    int wid  = tid >> 5;

    const float* col = g_probsT + ((size_t)(b*CC + crow + 1)) * AA;
    if (tid < 5) s_c5[tid] = 0;
    if (tid == 0) { s_nsel = 0; s_neq = 0; }

    int c0 = 0, c1 = 0, c2 = 0, c3 = 0, c4 = 0;
    for (int a = tid; a < AA; a += 512) {
        float p = col[a];
        float mval = (p > THRESH) ? p : -1.0f;
        unsigned u = __float_as_uint(mval);
        unsigned k = (u & 0x80000000u) ? ~u : (u | 0x80000000u);
        keys[a] = k;
        unsigned d = k >> 24;
        c0 += (d == 0xBFu); c1 += (d == 0xBEu); c2 += (d == 0xBDu);
        c3 += (d == 0xBCu); c4 += (d == 0x40u);
    }
    __syncthreads();
    {
        int w;
        w = __reduce_add_sync(FULL, c0); if (lane == 0 && w) atomicAdd(&s_c5[0], w);
        w = __reduce_add_sync(FULL, c1); if (lane == 0 && w) atomicAdd(&s_c5[1], w);
        w = __reduce_add_sync(FULL, c2); if (lane == 0 && w) atomicAdd(&s_c5[2], w);
        w = __reduce_add_sync(FULL, c3); if (lane == 0 && w) atomicAdd(&s_c5[3], w);
        w = __reduce_add_sync(FULL, c4); if (lane == 0 && w) atomicAdd(&s_c5[4], w);
    }
    __syncthreads();

    if (tid == 0) {
        const unsigned dg[5] = {0xBFu, 0xBEu, 0xBDu, 0xBCu, 0x40u};
        int cum = 0, need = KK;
        for (int j = 0; j < 5; j++) {
            int h = s_c5[j];
            if (cum + h >= need) {
                s_prefix = dg[j] << 24;
                s_pmask  = 0xFF000000u;
                s_need   = need - cum;
                break;
            }
            cum += h;
        }
    }
    __syncthreads();

#pragma unroll
    for (int pass = 0; pass < 3; pass++) {
        int shift = 16 - 8*pass;
        if (tid < 256) hist[tid] = 0;
        __syncthreads();
        unsigned pm = s_pmask, pf = s_prefix;
        for (int a = tid; a < AA; a += 512) {
            unsigned k = keys[a];
            if ((k & pm) == pf) atomicAdd(&hist[(k >> shift) & 255], 1);
        }
        __syncthreads();
        if (wid == 0) {
            int hi = 255 - 8*lane;
            int csum = 0;
#pragma unroll
            for (int k2 = 0; k2 < 8; k2++) csum += hist[hi - k2];
            int pfx = csum;
#pragma unroll
            for (int o = 1; o < 32; o <<= 1) {
                int v = __shfl_up_sync(FULL, pfx, o);
                if (lane >= o) pfx += v;
            }
            int excl = pfx - csum;
            int need = s_need;
            bool has = (excl < need) && (excl + csum >= need);
            unsigned mm = __ballot_sync(FULL, has);
            int owner = __ffs(mm) - 1;
            if (lane == owner) {
                int cum = excl;
#pragma unroll
                for (int k2 = 0; k2 < 8; k2++) {
                    int h = hist[hi - k2];
                    if (cum + h >= need) {
                        s_prefix = s_prefix | ((unsigned)(hi - k2) << shift);
                        s_pmask  = s_pmask | (255u << shift);
                        s_need   = need - cum;
                        break;
                    }
                    cum += h;
                }
            }
        }
        __syncthreads();
    }
    unsigned V = s_prefix;
    int needT  = s_need;

    for (int a = tid; a < AA; a += 512) {
        unsigned k = keys[a];
        if (k > V) {
            int pos = atomicAdd(&s_nsel, 1);
            sel[pos] = ((unsigned long long)k << 32) | (unsigned)(0xFFFFFFFFu - (unsigned)a);
        } else if (k == V) {
            int e = atomicAdd(&s_neq, 1);
            if (e < needT) {
                int pos = atomicAdd(&s_nsel, 1);
                sel[pos] = ((unsigned long long)k << 32) | (unsigned)(0xFFFFFFFFu - (unsigned)a);
            }
        }
    }
    __syncthreads();
    int nsel = s_nsel;
    if (tid >= nsel && tid < 512) sel[tid] = 0ULL;
    __syncthreads();

    // bitonic sort 512 desc, one element per thread
    for (int k2 = 2; k2 <= 512; k2 <<= 1) {
        for (int j = k2 >> 1; j > 0; j >>= 1) {
            int i = tid;
            int l = i ^ j;
            if (l > i) {
                unsigned long long x = sel[i], y = sel[l];
                bool desc = ((i & k2) == 0);
                if (desc ? (x < y) : (x > y)) { sel[i] = y; sel[l] = x; }
            }
            __syncthreads();
        }
    }

    for (int k = tid; k < KK; k += 512) {
        unsigned long long e = sel[k];
        unsigned vk = (unsigned)(e >> 32);
        unsigned a  = 0xFFFFFFFFu - (unsigned)(e & 0xFFFFFFFFu);
        unsigned u  = (vk & 0x80000000u) ? (vk & 0x7FFFFFFFu) : ~vk;
        float val   = __uint_as_float(u);
        size_t o = (size_t)b*NCAND + crow*KK + k;
        if (k < nsel && a < AA) {
            g_candVal[o] = val;
            g_candIdx[o] = (int)a;
            g_candBox[o] = g_boxes[(size_t)b*AA + a];
        } else {
            g_candVal[o] = -1.0f;
            g_candIdx[o] = 0;
            g_candBox[o] = make_float4(0.f,0.f,0.f,0.f);
        }
    }
}

// ---------------- kernel 3: matrix-NMS per (b,class), 512 threads, ragged M ----------------
__global__ void __launch_bounds__(512, 3) classnms_kernel() {
    __shared__ float4 s_box[KK2];
    __shared__ float2 s_hl[KK2];
    __shared__ float  s_ar[KK2], s_val[KK2];
    __shared__ unsigned s_M[32*(NWRD*(NWRD+1)/2)];  // ragged rows: 2912 words
    __shared__ int s_n;
    const unsigned FULL = 0xFFFFFFFFu;
    const float C_HI = 0.451f / 1.451f;
    const float C_LO = 0.449f / 1.449f;
    int tid  = threadIdx.x;
    int wid  = tid >> 5;          // 0..15
    int lane = tid & 31;
    int bi   = blockIdx.x;
    int b    = bi / NC;
    int crow = bi % NC;
    size_t base  = (size_t)b*NCAND + (size_t)crow*KK;
    size_t sbase = (size_t)(b*NC + crow)*KK;
    float off = __fmul_rn((float)(crow + 1), OFFV);

    for (int j = tid; j < KK2; j += 512) {
        float4 bx = make_float4(0.f,0.f,0.f,0.f);
        float v = -1.0f;
        if (j < KK) { bx = g_candBox[base + j]; v = g_candVal[base + j]; }
        float o0 = __fadd_rn(bx.x, off);
        float o1 = __fadd_rn(bx.y, off);
        float o2 = __fadd_rn(bx.z, off);
        float o3 = __fadd_rn(bx.w, off);
        float area = __fmul_rn(__fsub_rn(o2, o0), __fsub_rn(o3, o1));
        s_box[j] = make_float4(o0, o1, o2, o3);
        s_ar[j]  = area;
        float ap = __fadd_rn(area, 5e-10f);
        s_hl[j]  = make_float2(__fmul_rn(C_HI, ap), __fmul_rn(C_LO, ap));
        s_val[j] = v;
    }
    __syncthreads();

    if (wid == 0) {
        int n = KK;
#pragma unroll
        for (int t = 0; t < NWRD; t++) {
            int j = t*32 + lane;
            bool ok = (j < KK) && (s_val[j] > THRESH);
            unsigned m = __ballot_sync(FULL, ok);
            if (m != FULL) { n = t*32 + __ffs(~m) - 1; break; }
        }
        if (lane == 0) s_n = n;
    }
    __syncthreads();
    int n  = s_n;
    int nw = (n + 31) >> 5;

    // -------- Phase A: suppression-bit matrix (ragged rows, 16 warps) --------
    {
        int tt = 0;
        for (int ti = 0; ti < nw; ti++) {
            int tb = 32 * (NWRD*ti - ((ti*(ti-1)) >> 1));
            int rw = NWRD - ti;
            for (int tj = ti; tj < nw; tj++, tt++) {
                if ((tt & 15) != wid) continue;
                int j = tj*32 + lane;
                float4 jb  = s_box[j];
                float2 jhl = s_hl[j];
                int i0 = ti*32;
                int woff = tb + (tj - ti);
                unsigned bandacc = 0;
#pragma unroll 8
                for (int ii = 0; ii < 32; ii++) {
                    int i = i0 + ii;
                    float4 pb  = s_box[i];
                    float2 phl = s_hl[i];
                    float dx = __fsub_rn(fminf(pb.z, jb.z), fmaxf(pb.x, jb.x));
                    float dy = __fsub_rn(fminf(pb.w, jb.w), fmaxf(pb.y, jb.y));
                    float inter = __fmul_rn(fmaxf(dx, 0.0f), fmaxf(dy, 0.0f));
                    bool hi = inter > __fadd_rn(phl.x, jhl.x);
                    bool lo = inter > __fadd_rn(phl.y, jhl.y);
                    if (lo && !hi) bandacc |= (1u << ii);
                    unsigned mhi = __ballot_sync(FULL, hi);
                    if (ti == tj) mhi &= (0xFFFFFFFEu << ii);
                    if (lane == 0) s_M[woff + ii*rw] = mhi;
                }
                unsigned uw = bandacc;
#pragma unroll
                for (int o = 16; o > 0; o >>= 1) uw |= __shfl_xor_sync(FULL, uw, o);
                if (uw) {
                    while (uw) {
                        int ii = __ffs(uw) - 1; uw &= uw - 1;
                        int i = i0 + ii;
                        bool fix = false;
                        if ((bandacc >> ii) & 1u) {
                            float4 pb = s_box[i];
                            float dx = __fsub_rn(fminf(pb.z, jb.z), fmaxf(pb.x, jb.x));
                            float dy = __fsub_rn(fminf(pb.w, jb.w), fmaxf(pb.y, jb.y));
                            float inter = __fmul_rn(fmaxf(dx, 0.0f), fmaxf(dy, 0.0f));
                            float denom = __fadd_rn(__fsub_rn(__fadd_rn(s_ar[i], s_ar[j]), inter), 1e-9f);
                            fix = __fdiv_rn(inter, denom) > NMSV;
                        }
                        unsigned mfix = __ballot_sync(FULL, fix);
                        if (ti == tj) mfix &= (0xFFFFFFFEu << ii);
                        if (lane == 0 && mfix) s_M[woff + ii*rw] |= mfix;
                    }
                }
            }
        }
    }
    __syncthreads();

    // -------- Phase B: greedy bit-walk (warp 0) --------
    if (wid == 0) {
        unsigned alive = 0;
        if (lane < nw) {
            int lo0 = lane*32;
            int nb = n - lo0;
            alive = (nb >= 32) ? FULL : ((nb > 0) ? ((1u << nb) - 1u) : 0u);
        }
        int cnt = 0;
        while (cnt < DD) {
            unsigned act = __ballot_sync(FULL, alive != 0u);
            if (!act) break;
            int wt = __ffs(act) - 1;
            unsigned aw = __shfl_sync(FULL, alive, wt);
            int bit = __ffs(aw) - 1;
            int i = wt*32 + bit;
            if (lane == 0) {
                g_survVal[sbase + cnt] = s_val[i];
                g_survK  [sbase + cnt] = i;
            }
            cnt++;
            if (lane == wt) alive &= ~(1u << bit);
            int ti2 = i >> 5;
            int rb  = 32 * (NWRD*ti2 - ((ti2*(ti2-1)) >> 1)) + (i & 31) * (NWRD - ti2);
            unsigned m = (lane >= ti2 && lane < NWRD) ? s_M[rb + lane - ti2] : 0u;
            alive &= ~m;
        }
        if (lane == 0) g_survCnt[b*NC + crow] = cnt;
    }
}

// ---------------- kernel 4: parallel merge, 1024 threads ----------------
__global__ void __launch_bounds__(1024) merge_kernel() {
    extern __shared__ unsigned long long keys[];       // [MKEY_N]
    __shared__ unsigned long long cand[1024];
    __shared__ int hist[256];
    __shared__ int s_cnt[NC];
    __shared__ int s_c4[4];
    __shared__ unsigned s_prefix, s_pmask;
    __shared__ int s_need, s_m, s_ntot;
    const unsigned FULL = 0xFFFFFFFFu;
    int b = blockIdx.x, tid = threadIdx.x;
    int lane = tid & 31, wid = tid >> 5;

    if (tid < NC) s_cnt[tid] = g_survCnt[b*NC + tid];
    if (tid < 4) s_c4[tid] = 0;
    if (tid == 0) { s_m = 0; s_ntot = 0; }
    __syncthreads();
    if (tid < 32) {
        int t = 0;
        for (int c = lane; c < NC; c += 32) t += s_cnt[c];
        for (int o = 16; o > 0; o >>= 1) t += __shfl_down_sync(FULL, t, o);
        if (lane == 0) s_ntot = t;
    }

    int c0 = 0, c1 = 0, c2 = 0, c3 = 0;
    for (int idx = tid; idx < MKEY_N; idx += 1024) {
        int c = idx / 200, t = idx - c*200;
        unsigned long long k = 0ULL;
        if (t < s_cnt[c]) {
            float v  = g_survVal[(size_t)(b*NC + c)*KK + t];
            int   ki = g_survK  [(size_t)(b*NC + c)*KK + t];
            unsigned vf   = __float_as_uint(v) | 0x80000000u;
            unsigned flat = (unsigned)(c*KK + ki);
            k = ((unsigned long long)vf << 32) | (0xFFFFFFFFu - flat);
            unsigned d = vf >> 24;
            c0 += (d == 0xBFu); c1 += (d == 0xBEu); c2 += (d == 0xBDu); c3 += (d == 0xBCu);
        }
        keys[idx] = k;
    }
    {
        int w;
        w = __reduce_add_sync(FULL, c0); if (lane == 0 && w) atomicAdd(&s_c4[0], w);
        w = __reduce_add_sync(FULL, c1); if (lane == 0 && w) atomicAdd(&s_c4[1], w);
        w = __reduce_add_sync(FULL, c2); if (lane == 0 && w) atomicAdd(&s_c4[2], w);
        w = __reduce_add_sync(FULL, c3); if (lane == 0 && w) atomicAdd(&s_c4[3], w);
    }
    __syncthreads();
    int ntot = s_ntot;

    unsigned V;
    if (ntot >= DD) {
        if (tid == 0) {
            const unsigned dg[4] = {0xBFu, 0xBEu, 0xBDu, 0xBCu};
            int cum = 0, need = DD;
            for (int j = 0; j < 4; j++) {
                int h = s_c4[j];
                if (cum + h >= need) {
                    s_prefix = dg[j] << 24;
                    s_pmask  = 0xFF000000u;
                    s_need   = need - cum;
                    break;
                }
                cum += h;
            }
        }
        __syncthreads();
#pragma unroll
        for (int pass = 0; pass < 3; pass++) {
            int shift = 16 - 8*pass;
            if (tid < 256) hist[tid] = 0;
            __syncthreads();
            unsigned pm = s_pmask, pf = s_prefix;
            for (int idx = tid; idx < MKEY_N; idx += 1024) {
                unsigned hv = (unsigned)(keys[idx] >> 32);
                if ((hv & pm) == pf) atomicAdd(&hist[(hv >> shift) & 255], 1);
            }
            __syncthreads();
            if (wid == 0) {
                int hi = 255 - 8*lane;
                int csum = 0;
#pragma unroll
                for (int k2 = 0; k2 < 8; k2++) csum += hist[hi - k2];
                int pfx = csum;
#pragma unroll
                for (int o = 1; o < 32; o <<= 1) {
                    int v = __shfl_up_sync(FULL, pfx, o);
                    if (lane >= o) pfx += v;
                }
                int excl = pfx - csum;
                int need = s_need;
                bool has = (excl < need) && (excl + csum >= need);
                unsigned mm = __ballot_sync(FULL, has);
                int owner = __ffs(mm) - 1;
                if (lane == owner) {
                    int cum = excl;
#pragma unroll
                    for (int k2 = 0; k2 < 8; k2++) {
                        int h = hist[hi - k2];
                        if (cum + h >= need) {
                            s_prefix = s_prefix | ((unsigned)(hi - k2) << shift);
                            s_pmask  = s_pmask | (255u << shift);
                            s_need   = need - cum;
                            break;
                        }
                        cum += h;
                    }
                }
            }
            __syncthreads();
        }
        V = s_prefix;
    } else {
        V = 1u;
        __syncthreads();
    }

    for (int idx = tid; idx < MKEY_N; idx += 1024) {
        unsigned hv = (unsigned)(keys[idx] >> 32);
        if (hv >= V) {
            int p = atomicAdd(&s_m, 1);
            if (p < 1024) cand[p] = keys[idx];
        }
    }
    __syncthreads();
    int mc = s_m; if (mc > 1024) mc = 1024;
    for (int p = mc + tid; p < 1024; p += 1024) cand[p] = 0ULL;
    __syncthreads();

    for (int k2 = 2; k2 <= 1024; k2 <<= 1) {
        for (int j = k2 >> 1; j > 0; j >>= 1) {
            int i = tid;
            int l = i ^ j;
            if (l > i) {
                unsigned long long x = cand[i], y = cand[l];
                bool desc = ((i & k2) == 0);
                if (desc ? (x < y) : (x > y)) { cand[i] = y; cand[l] = x; }
            }
            __syncthreads();
        }
    }

    for (int r = tid; r < DD; r += 1024) {
        unsigned long long k = (r < mc) ? cand[r] : 0ULL;
        int flat = -1;
        if (k != 0ULL) flat = (int)(0xFFFFFFFFu - (unsigned)(k & 0xFFFFFFFFu));
        g_keepFlat[b*DD + r] = flat;
    }
}

// ---------------- kernel 5: output assembly (one warp per kept row) ----------------
__global__ void output_kernel(float* __restrict__ out, int mode) {
    int wg   = blockIdx.x * (blockDim.x >> 5) + (threadIdx.x >> 5);
    int lane = threadIdx.x & 31;
    if (wg >= BB*DD) return;
    int b = wg / DD, r = wg % DD;
    float* ob = 0; float* os = 0; float* ol = 0;
    if (mode == 0) {
        ob = out + (size_t)(b*DD + r)*4;
        os = out + (size_t)BB*DD*4 + (size_t)(b*DD + r)*2;
        ol = out + (size_t)BB*DD*6 + (size_t)(b*DD + r)*2;
    } else if (mode == 1) {
        ob = out + (size_t)(b*DD + r)*4;
    } else {
        os = out + (size_t)(b*DD + r)*2;
    }
    int flat = g_keepFlat[b*DD + r];
    if (flat < 0) {
        if (lane == 0) {
            if (ob) { ob[0]=0.f; ob[1]=0.f; ob[2]=0.f; ob[3]=0.f; }
            if (os) { os[0]=0.f; os[1]=0.f; }
            if (ol) { ol[0]=0.f; ol[1]=0.f; }
        }
        return;
    }
    size_t co = (size_t)b*NCAND + flat;
    if (lane == 0 && ob) {
        float4 bx = g_candBox[co];
        ob[0] = bx.x; ob[1] = bx.y; ob[2] = bx.z; ob[3] = bx.w;
    }
    if (!os && !ol) return;
    int anchor = g_candIdx[co];
    float va[3]; int ia[3];
#pragma unroll
    for (int s = 0; s < 3; s++) {
        int c = 1 + lane + 32*s;
        if (c <= NC) { va[s] = g_probsT[((size_t)(b*CC + c))*AA + anchor]; ia[s] = c; }
        else         { va[s] = NEGINF; ia[s] = 1 << 20; }
    }
    float f1v = va[0], f2v = NEGINF;
    int   f1i = ia[0], f2i = 1 << 20;
#pragma unroll
    for (int s = 1; s < 3; s++) {
        if (va[s] > f1v)      { f2v = f1v; f2i = f1i; f1v = va[s]; f1i = ia[s]; }
        else if (va[s] > f2v) { f2v = va[s]; f2i = ia[s]; }
    }
    for (int o = 16; o > 0; o >>= 1) {
        float o1v = __shfl_down_sync(0xFFFFFFFFu, f1v, o);
        int   o1i = __shfl_down_sync(0xFFFFFFFFu, f1i, o);
        float o2v = __shfl_down_sync(0xFFFFFFFFu, f2v, o);
        int   o2i = __shfl_down_sync(0xFFFFFFFFu, f2i, o);
        bool a_first = (f1v > o1v) || (f1v == o1v && f1i < o1i);
        float n1v, n2v; int n1i, n2i;
        if (a_first) {
            n1v = f1v; n1i = f1i;
            bool pick = (f2v > o1v) || (f2v == o1v && f2i < o1i);
            n2v = pick ? f2v : o1v; n2i = pick ? f2i : o1i;
        } else {
            n1v = o1v; n1i = o1i;
            bool pick = (o2v > f1v) || (o2v == f1v && o2i < f1i);
            n2v = pick ? o2v : f1v; n2i = pick ? o2i : f1i;
        }
        f1v = n1v; f1i = n1i; f2v = n2v; f2i = n2i;
    }
    if (lane == 0) {
        if (os) { os[0] = f1v; os[1] = f2v; }
        if (ol) { ol[0] = (float)f1i; ol[1] = (float)f2i; }
    }
}

// ---------------- launcher ----------------
extern "C" void kernel_launch(void* const* d_in, const int* in_sizes, int n_in,
                              void* d_out, int out_size) {
    const float* logits  = (const float*)d_in[0];   // (B, A, C)
    const float* rel     = (const float*)d_in[1];   // (B, A, 4)
    const float* anchors = (const float*)d_in[2];   // (A, 4)
    float* out = (float*)d_out;
    int mode = (out_size == BB*DD*8) ? 0 : ((out_size == BB*DD*4) ? 1 : 2);

    dim3 gs((AA + 127)/128, BB);
    softmax_kernel<<<gs, 256>>>(logits, rel, anchors);

    dim3 gt(NC, BB);
    topk_kernel<<<gt, 512>>>();

    classnms_kernel<<<BB*NC, 512>>>();

    (void)cudaFuncSetAttribute(merge_kernel,
                               cudaFuncAttributeMaxDynamicSharedMemorySize,
                               MKEY_N*8);
    merge_kernel<<<BB, 1024, MKEY_N*8>>>();

    output_kernel<<<(BB*DD)/8, 256>>>(out, mode);
}

// round 17
// speedup vs baseline: 1.1963x; 1.1963x over previous
#include <cuda_runtime.h>
#include <math.h>

#define BB 16
#define AA 8732
#define CC 91
#define NC 90
#define KK 400
#define KK2 416          /* padded to 13 full warps */
#define NWRD 13
#define NCAND (NC*KK)
#define DD 200
#define MKEY_N (NC*200)  /* 18000 merge keys per image */
#define IMGV 300.0f
#define OFFV 302.0f
#define THRESH 0.01f
#define NMSV 0.45f
#define NEGINF (-1e30f)
#define CLIPV 4.135166556742356f

// ---------------- scratch (device globals; no allocation) ----------------
__device__ float  g_probsT[(size_t)BB*CC*AA];
__device__ float4 g_boxes[BB*AA];
__device__ float  g_candVal[BB*NCAND];
__device__ int    g_candIdx[BB*NCAND];
__device__ float4 g_candBox[BB*NCAND];
__device__ float  g_survVal[(size_t)BB*NC*KK];
__device__ int    g_survK[(size_t)BB*NC*KK];
__device__ int    g_survCnt[BB*NC];
__device__ int    g_keepFlat[BB*DD];

// ---------------- kernel 1: softmax (class-split x2) + fused box decode ----------------
__global__ void softmax_kernel(const float* __restrict__ logits,
                               const float* __restrict__ rel,
                               const float* __restrict__ anchors) {
    __shared__ float s[CC * 129];
    const unsigned FULL = 0xFFFFFFFFu;
    int b = blockIdx.y;
    int a0 = blockIdx.x * 128;
    int na = AA - a0; if (na > 128) na = 128;
    int tid = threadIdx.x;
    int al   = tid >> 1;
    int half = tid & 1;

    if (tid < na) {
        int a = a0 + tid;
        int i = b*AA + a;
        float4 an = ((const float4*)anchors)[a];
        float4 rg = ((const float4*)rel)[i];
        float wa  = __fsub_rn(an.z, an.x);
        float ha  = __fsub_rn(an.w, an.y);
        float cxa = __fadd_rn(an.x, __fmul_rn(0.5f, wa));
        float cya = __fadd_rn(an.y, __fmul_rn(0.5f, ha));
        float dx  = __fdiv_rn(rg.x, 10.0f);
        float dy  = __fdiv_rn(rg.y, 10.0f);
        float dw  = fminf(__fdiv_rn(rg.z, 5.0f), CLIPV);
        float dh  = fminf(__fdiv_rn(rg.w, 5.0f), CLIPV);
        float cx  = __fadd_rn(__fmul_rn(dx, wa), cxa);
        float cy  = __fadd_rn(__fmul_rn(dy, ha), cya);
        float w   = __fmul_rn(expf(dw), wa);
        float h   = __fmul_rn(expf(dh), ha);
        float4 o;
        o.x = fminf(fmaxf(__fsub_rn(cx, __fmul_rn(0.5f, w)), 0.0f), IMGV);
        o.y = fminf(fmaxf(__fsub_rn(cy, __fmul_rn(0.5f, h)), 0.0f), IMGV);
        o.z = fminf(fmaxf(__fadd_rn(cx, __fmul_rn(0.5f, w)), 0.0f), IMGV);
        o.w = fminf(fmaxf(__fadd_rn(cy, __fmul_rn(0.5f, h)), 0.0f), IMGV);
        g_boxes[i] = o;
    }

    const float* base = logits + (size_t)(b*AA + a0) * CC;
    for (int idx = tid; idx < na * CC; idx += 256) {
        int a2 = idx / CC;
        int c  = idx - a2 * CC;
        s[c * 129 + a2] = base[idx];
    }
    __syncthreads();

    {   // ALL threads execute (shfl stays warp-uniform)
        int c_beg = half ? 46 : 0;
        int c_end = half ? CC : 46;
        float m = NEGINF;
        for (int c = c_beg; c < c_end; c++) m = fmaxf(m, s[c*129 + al]);
        float mo = __shfl_xor_sync(FULL, m, 1);
        m = fmaxf(m, mo);
        float sum = 0.0f;
        for (int c = c_beg; c < c_end; c++) {
            float e = expf(__fsub_rn(s[c*129 + al], m));
            s[c*129 + al] = e;
            sum = __fadd_rn(sum, e);
        }
        float so = __shfl_xor_sync(FULL, sum, 1);
        float s0 = half ? so : sum;
        float s1 = half ? sum : so;
        float tot = __fadd_rn(s0, s1);
        float rs = __frcp_rn(tot);
        for (int c = c_beg; c < c_end; c++)
            s[c*129 + al] = __fmul_rn(s[c*129 + al], rs);
    }
    __syncthreads();

    for (int idx = tid; idx < CC*128; idx += 256) {
        int c = idx >> 7;
        int a = idx & 127;
        if (a < na)
            g_probsT[((size_t)(b*CC + c))*AA + a0 + a] = s[c*129 + a];
    }
}

// ---------------- kernel 2: per-(b,class) top-400  [R15 internals] ----------------
__global__ void topk_kernel() {
    __shared__ unsigned keys[AA];
    __shared__ unsigned long long sel[512];
    __shared__ int hist[256];
    __shared__ int s_c5[5];
    __shared__ unsigned s_prefix, s_pmask;
    __shared__ int s_need, s_nsel, s_neq;
    const unsigned FULL = 0xFFFFFFFFu;
    int crow = blockIdx.x;   // class-1
    int b    = blockIdx.y;
    int tid  = threadIdx.x;
    int lane = tid & 31;
    int wid  = tid >> 5;

    const float* col = g_probsT + ((size_t)(b*CC + crow + 1)) * AA;
    if (tid < 5) s_c5[tid] = 0;
    if (tid == 0) { s_nsel = 0; s_neq = 0; }

    int c0 = 0, c1 = 0, c2 = 0, c3 = 0, c4 = 0;
    for (int a = tid; a < AA; a += 256) {
        float p = col[a];
        float mval = (p > THRESH) ? p : -1.0f;
        unsigned u = __float_as_uint(mval);
        unsigned k = (u & 0x80000000u) ? ~u : (u | 0x80000000u);
        keys[a] = k;
        unsigned d = k >> 24;
        c0 += (d == 0xBFu); c1 += (d == 0xBEu); c2 += (d == 0xBDu);
        c3 += (d == 0xBCu); c4 += (d == 0x40u);
    }
    __syncthreads();
    {
        int w;
        w = __reduce_add_sync(FULL, c0); if (lane == 0 && w) atomicAdd(&s_c5[0], w);
        w = __reduce_add_sync(FULL, c1); if (lane == 0 && w) atomicAdd(&s_c5[1], w);
        w = __reduce_add_sync(FULL, c2); if (lane == 0 && w) atomicAdd(&s_c5[2], w);
        w = __reduce_add_sync(FULL, c3); if (lane == 0 && w) atomicAdd(&s_c5[3], w);
        w = __reduce_add_sync(FULL, c4); if (lane == 0 && w) atomicAdd(&s_c5[4], w);
    }
    __syncthreads();

    if (tid == 0) {
        const unsigned dg[5] = {0xBFu, 0xBEu, 0xBDu, 0xBCu, 0x40u};
        int cum = 0, need = KK;
        for (int j = 0; j < 5; j++) {
            int h = s_c5[j];
            if (cum + h >= need) {
                s_prefix = dg[j] << 24;
                s_pmask  = 0xFF000000u;
                s_need   = need - cum;
                break;
            }
            cum += h;
        }
    }
    __syncthreads();

#pragma unroll
    for (int pass = 0; pass < 3; pass++) {
        int shift = 16 - 8*pass;
        if (tid < 256) hist[tid] = 0;
        __syncthreads();
        unsigned pm = s_pmask, pf = s_prefix;
        for (int a = tid; a < AA; a += 256) {
            unsigned k = keys[a];
            if ((k & pm) == pf) atomicAdd(&hist[(k >> shift) & 255], 1);
        }
        __syncthreads();
        if (wid == 0) {
            int hi = 255 - 8*lane;
            int csum = 0;
#pragma unroll
            for (int k2 = 0; k2 < 8; k2++) csum += hist[hi - k2];
            int pfx = csum;
#pragma unroll
            for (int o = 1; o < 32; o <<= 1) {
                int v = __shfl_up_sync(FULL, pfx, o);
                if (lane >= o) pfx += v;
            }
            int excl = pfx - csum;
            int need = s_need;
            bool has = (excl < need) && (excl + csum >= need);
            unsigned mm = __ballot_sync(FULL, has);
            int owner = __ffs(mm) - 1;
            if (lane == owner) {
                int cum = excl;
#pragma unroll
                for (int k2 = 0; k2 < 8; k2++) {
                    int h = hist[hi - k2];
                    if (cum + h >= need) {
                        s_prefix = s_prefix | ((unsigned)(hi - k2) << shift);
                        s_pmask  = s_pmask | (255u << shift);
                        s_need   = need - cum;
                        break;
                    }
                    cum += h;
                }
            }
        }
        __syncthreads();
    }
    unsigned V = s_prefix;
    int needT  = s_need;

    for (int a = tid; a < AA; a += 256) {
        unsigned k = keys[a];
        if (k > V) {
            int pos = atomicAdd(&s_nsel, 1);
            sel[pos] = ((unsigned long long)k << 32) | (unsigned)(0xFFFFFFFFu - (unsigned)a);
        } else if (k == V) {
            int e = atomicAdd(&s_neq, 1);
            if (e < needT) {
                int pos = atomicAdd(&s_nsel, 1);
                sel[pos] = ((unsigned long long)k << 32) | (unsigned)(0xFFFFFFFFu - (unsigned)a);
            }
        }
    }
    __syncthreads();
    int nsel = s_nsel;
    for (int p = nsel + tid; p < 512; p += 256) sel[p] = 0ULL;
    __syncthreads();

    for (int k2 = 2; k2 <= 512; k2 <<= 1) {
        for (int j = k2 >> 1; j > 0; j >>= 1) {
            for (int i = tid; i < 512; i += 256) {
                int l = i ^ j;
                if (l > i) {
                    unsigned long long x = sel[i], y = sel[l];
                    bool desc = ((i & k2) == 0);
                    if (desc ? (x < y) : (x > y)) { sel[i] = y; sel[l] = x; }
                }
            }
            __syncthreads();
        }
    }

    for (int k = tid; k < KK; k += 256) {
        unsigned long long e = sel[k];
        unsigned vk = (unsigned)(e >> 32);
        unsigned a  = 0xFFFFFFFFu - (unsigned)(e & 0xFFFFFFFFu);
        unsigned u  = (vk & 0x80000000u) ? (vk & 0x7FFFFFFFu) : ~vk;
        float val   = __uint_as_float(u);
        size_t o = (size_t)b*NCAND + crow*KK + k;
        if (k < nsel && a < AA) {
            g_candVal[o] = val;
            g_candIdx[o] = (int)a;
            g_candBox[o] = g_boxes[(size_t)b*AA + a];
        } else {
            g_candVal[o] = -1.0f;
            g_candIdx[o] = 0;
            g_candBox[o] = make_float4(0.f,0.f,0.f,0.f);
        }
    }
}

// ---------------- kernel 3: matrix-NMS per (b,class), ragged M ----------------
// R15 structure; the two per-pair threshold adds are fused into one packed
// add.rn.f32x2 (per-lane rn rounding -> bit-identical to two __fadd_rn).
__global__ void __launch_bounds__(256, 6) classnms_kernel() {
    __shared__ float4 s_box[KK2];
    __shared__ float2 s_hl[KK2];
    __shared__ float  s_ar[KK2], s_val[KK2];
    __shared__ unsigned s_M[32*(NWRD*(NWRD+1)/2)];  // ragged rows: 2912 words
    __shared__ int s_n;
    const unsigned FULL = 0xFFFFFFFFu;
    const float C_HI = 0.451f / 1.451f;
    const float C_LO = 0.449f / 1.449f;
    int tid  = threadIdx.x;
    int wid  = tid >> 5;
    int lane = tid & 31;
    int bi   = blockIdx.x;
    int b    = bi / NC;
    int crow = bi % NC;
    size_t base  = (size_t)b*NCAND + (size_t)crow*KK;
    size_t sbase = (size_t)(b*NC + crow)*KK;
    float off = __fmul_rn((float)(crow + 1), OFFV);

    for (int j = tid; j < KK2; j += 256) {
        float4 bx = make_float4(0.f,0.f,0.f,0.f);
        float v = -1.0f;
        if (j < KK) { bx = g_candBox[base + j]; v = g_candVal[base + j]; }
        float o0 = __fadd_rn(bx.x, off);
        float o1 = __fadd_rn(bx.y, off);
        float o2 = __fadd_rn(bx.z, off);
        float o3 = __fadd_rn(bx.w, off);
        float area = __fmul_rn(__fsub_rn(o2, o0), __fsub_rn(o3, o1));
        s_box[j] = make_float4(o0, o1, o2, o3);
        s_ar[j]  = area;
        float ap = __fadd_rn(area, 5e-10f);
        s_hl[j]  = make_float2(__fmul_rn(C_HI, ap), __fmul_rn(C_LO, ap));
        s_val[j] = v;
    }
    __syncthreads();

    if (wid == 0) {
        int n = KK;
#pragma unroll
        for (int t = 0; t < NWRD; t++) {
            int j = t*32 + lane;
            bool ok = (j < KK) && (s_val[j] > THRESH);
            unsigned m = __ballot_sync(FULL, ok);
            if (m != FULL) { n = t*32 + __ffs(~m) - 1; break; }
        }
        if (lane == 0) s_n = n;
    }
    __syncthreads();
    int n  = s_n;
    int nw = (n + 31) >> 5;

    // -------- Phase A: suppression-bit matrix (ragged rows) --------
    {
        int tt = 0;
        for (int ti = 0; ti < nw; ti++) {
            int tb = 32 * (NWRD*ti - ((ti*(ti-1)) >> 1));
            int rw = NWRD - ti;
            for (int tj = ti; tj < nw; tj++, tt++) {
                if ((tt & 7) != wid) continue;
                int j = tj*32 + lane;
                float4 jb  = s_box[j];
                float2 jhl = s_hl[j];
                unsigned long long jpack;
                asm("mov.b64 %0, {%1, %2};" : "=l"(jpack) : "f"(jhl.x), "f"(jhl.y));
                int i0 = ti*32;
                int woff = tb + (tj - ti);
                unsigned bandacc = 0;
#pragma unroll 8
                for (int ii = 0; ii < 32; ii++) {
                    int i = i0 + ii;
                    float4 pb  = s_box[i];
                    float2 phl = s_hl[i];
                    float dx = __fsub_rn(fminf(pb.z, jb.z), fmaxf(pb.x, jb.x));
                    float dy = __fsub_rn(fminf(pb.w, jb.w), fmaxf(pb.y, jb.y));
                    float inter = __fmul_rn(fmaxf(dx, 0.0f), fmaxf(dy, 0.0f));
                    unsigned long long ppack, th;
                    asm("mov.b64 %0, {%1, %2};" : "=l"(ppack) : "f"(phl.x), "f"(phl.y));
                    asm("add.rn.f32x2 %0, %1, %2;" : "=l"(th) : "l"(ppack), "l"(jpack));
                    float thx, thy;
                    asm("mov.b64 {%0, %1}, %2;" : "=f"(thx), "=f"(thy) : "l"(th));
                    bool hi = inter > thx;
                    bool lo = inter > thy;
                    if (lo && !hi) bandacc |= (1u << ii);
                    unsigned mhi = __ballot_sync(FULL, hi);
                    if (ti == tj) mhi &= (0xFFFFFFFEu << ii);
                    if (lane == 0) s_M[woff + ii*rw] = mhi;
                }
                unsigned uw = bandacc;
#pragma unroll
                for (int o = 16; o > 0; o >>= 1) uw |= __shfl_xor_sync(FULL, uw, o);
                if (uw) {
                    while (uw) {
                        int ii = __ffs(uw) - 1; uw &= uw - 1;
                        int i = i0 + ii;
                        bool fix = false;
                        if ((bandacc >> ii) & 1u) {
                            float4 pb = s_box[i];
                            float dx = __fsub_rn(fminf(pb.z, jb.z), fmaxf(pb.x, jb.x));
                            float dy = __fsub_rn(fminf(pb.w, jb.w), fmaxf(pb.y, jb.y));
                            float inter = __fmul_rn(fmaxf(dx, 0.0f), fmaxf(dy, 0.0f));
                            float denom = __fadd_rn(__fsub_rn(__fadd_rn(s_ar[i], s_ar[j]), inter), 1e-9f);
                            fix = __fdiv_rn(inter, denom) > NMSV;
                        }
                        unsigned mfix = __ballot_sync(FULL, fix);
                        if (ti == tj) mfix &= (0xFFFFFFFEu << ii);
                        if (lane == 0 && mfix) s_M[woff + ii*rw] |= mfix;
                    }
                }
            }
        }
    }
    __syncthreads();

    // -------- Phase B: greedy bit-walk (warp 0) --------
    if (wid == 0) {
        unsigned alive = 0;
        if (lane < nw) {
            int lo0 = lane*32;
            int nb = n - lo0;
            alive = (nb >= 32) ? FULL : ((nb > 0) ? ((1u << nb) - 1u) : 0u);
        }
        int cnt = 0;
        while (cnt < DD) {
            unsigned act = __ballot_sync(FULL, alive != 0u);
            if (!act) break;
            int wt = __ffs(act) - 1;
            unsigned aw = __shfl_sync(FULL, alive, wt);
            int bit = __ffs(aw) - 1;
            int i = wt*32 + bit;
            if (lane == 0) {
                g_survVal[sbase + cnt] = s_val[i];
                g_survK  [sbase + cnt] = i;
            }
            cnt++;
            if (lane == wt) alive &= ~(1u << bit);
            int ti2 = i >> 5;
            int rb  = 32 * (NWRD*ti2 - ((ti2*(ti2-1)) >> 1)) + (i & 31) * (NWRD - ti2);
            unsigned m = (lane >= ti2 && lane < NWRD) ? s_M[rb + lane - ti2] : 0u;
            alive &= ~m;
        }
        if (lane == 0) g_survCnt[b*NC + crow] = cnt;
    }
}

// ---------------- kernel 4: parallel merge, 1024 threads ----------------
__global__ void __launch_bounds__(1024) merge_kernel() {
    extern __shared__ unsigned long long keys[];       // [MKEY_N]
    __shared__ unsigned long long cand[1024];
    __shared__ int hist[256];
    __shared__ int s_cnt[NC];
    __shared__ int s_c4[4];
    __shared__ unsigned s_prefix, s_pmask;
    __shared__ int s_need, s_m, s_ntot;
    const unsigned FULL = 0xFFFFFFFFu;
    int b = blockIdx.x, tid = threadIdx.x;
    int lane = tid & 31, wid = tid >> 5;

    if (tid < NC) s_cnt[tid] = g_survCnt[b*NC + tid];
    if (tid < 4) s_c4[tid] = 0;
    if (tid == 0) { s_m = 0; s_ntot = 0; }
    __syncthreads();
    if (tid < 32) {
        int t = 0;
        for (int c = lane; c < NC; c += 32) t += s_cnt[c];
        for (int o = 16; o > 0; o >>= 1) t += __shfl_down_sync(FULL, t, o);
        if (lane == 0) s_ntot = t;
    }

    int c0 = 0, c1 = 0, c2 = 0, c3 = 0;
    for (int idx = tid; idx < MKEY_N; idx += 1024) {
        int c = idx / 200, t = idx - c*200;
        unsigned long long k = 0ULL;
        if (t < s_cnt[c]) {
            float v  = g_survVal[(size_t)(b*NC + c)*KK + t];
            int   ki = g_survK  [(size_t)(b*NC + c)*KK + t];
            unsigned vf   = __float_as_uint(v) | 0x80000000u;
            unsigned flat = (unsigned)(c*KK + ki);
            k = ((unsigned long long)vf << 32) | (0xFFFFFFFFu - flat);
            unsigned d = vf >> 24;
            c0 += (d == 0xBFu); c1 += (d == 0xBEu); c2 += (d == 0xBDu); c3 += (d == 0xBCu);
        }
        keys[idx] = k;
    }
    {
        int w;
        w = __reduce_add_sync(FULL, c0); if (lane == 0 && w) atomicAdd(&s_c4[0], w);
        w = __reduce_add_sync(FULL, c1); if (lane == 0 && w) atomicAdd(&s_c4[1], w);
        w = __reduce_add_sync(FULL, c2); if (lane == 0 && w) atomicAdd(&s_c4[2], w);
        w = __reduce_add_sync(FULL, c3); if (lane == 0 && w) atomicAdd(&s_c4[3], w);
    }
    __syncthreads();
    int ntot = s_ntot;

    unsigned V;
    if (ntot >= DD) {
        if (tid == 0) {
            const unsigned dg[4] = {0xBFu, 0xBEu, 0xBDu, 0xBCu};
            int cum = 0, need = DD;
            for (int j = 0; j < 4; j++) {
                int h = s_c4[j];
                if (cum + h >= need) {
                    s_prefix = dg[j] << 24;
                    s_pmask  = 0xFF000000u;
                    s_need   = need - cum;
                    break;
                }
                cum += h;
            }
        }
        __syncthreads();
#pragma unroll
        for (int pass = 0; pass < 3; pass++) {
            int shift = 16 - 8*pass;
            if (tid < 256) hist[tid] = 0;
            __syncthreads();
            unsigned pm = s_pmask, pf = s_prefix;
            for (int idx = tid; idx < MKEY_N; idx += 1024) {
                unsigned hv = (unsigned)(keys[idx] >> 32);
                if ((hv & pm) == pf) atomicAdd(&hist[(hv >> shift) & 255], 1);
            }
            __syncthreads();
            if (wid == 0) {
                int hi = 255 - 8*lane;
                int csum = 0;
#pragma unroll
                for (int k2 = 0; k2 < 8; k2++) csum += hist[hi - k2];
                int pfx = csum;
#pragma unroll
                for (int o = 1; o < 32; o <<= 1) {
                    int v = __shfl_up_sync(FULL, pfx, o);
                    if (lane >= o) pfx += v;
                }
                int excl = pfx - csum;
                int need = s_need;
                bool has = (excl < need) && (excl + csum >= need);
                unsigned mm = __ballot_sync(FULL, has);
                int owner = __ffs(mm) - 1;
                if (lane == owner) {
                    int cum = excl;
#pragma unroll
                    for (int k2 = 0; k2 < 8; k2++) {
                        int h = hist[hi - k2];
                        if (cum + h >= need) {
                            s_prefix = s_prefix | ((unsigned)(hi - k2) << shift);
                            s_pmask  = s_pmask | (255u << shift);
                            s_need   = need - cum;
                            break;
                        }
                        cum += h;
                    }
                }
            }
            __syncthreads();
        }
        V = s_prefix;
    } else {
        V = 1u;
        __syncthreads();
    }

    for (int idx = tid; idx < MKEY_N; idx += 1024) {
        unsigned hv = (unsigned)(keys[idx] >> 32);
        if (hv >= V) {
            int p = atomicAdd(&s_m, 1);
            if (p < 1024) cand[p] = keys[idx];
        }
    }
    __syncthreads();
    int mc = s_m; if (mc > 1024) mc = 1024;
    for (int p = mc + tid; p < 1024; p += 1024) cand[p] = 0ULL;
    __syncthreads();

    for (int k2 = 2; k2 <= 1024; k2 <<= 1) {
        for (int j = k2 >> 1; j > 0; j >>= 1) {
            int i = tid;
            int l = i ^ j;
            if (l > i) {
                unsigned long long x = cand[i], y = cand[l];
                bool desc = ((i & k2) == 0);
                if (desc ? (x < y) : (x > y)) { cand[i] = y; cand[l] = x; }
            }
            __syncthreads();
        }
    }

    for (int r = tid; r < DD; r += 1024) {
        unsigned long long k = (r < mc) ? cand[r] : 0ULL;
        int flat = -1;
        if (k != 0ULL) flat = (int)(0xFFFFFFFFu - (unsigned)(k & 0xFFFFFFFFu));
        g_keepFlat[b*DD + r] = flat;
    }
}

// ---------------- kernel 5: output assembly (one warp per kept row) ----------------
__global__ void output_kernel(float* __restrict__ out, int mode) {
    int wg   = blockIdx.x * (blockDim.x >> 5) + (threadIdx.x >> 5);
    int lane = threadIdx.x & 31;
    if (wg >= BB*DD) return;
    int b = wg / DD, r = wg % DD;
    float* ob = 0; float* os = 0; float* ol = 0;
    if (mode == 0) {
        ob = out + (size_t)(b*DD + r)*4;
        os = out + (size_t)BB*DD*4 + (size_t)(b*DD + r)*2;
        ol = out + (size_t)BB*DD*6 + (size_t)(b*DD + r)*2;
    } else if (mode == 1) {
        ob = out + (size_t)(b*DD + r)*4;
    } else {
        os = out + (size_t)(b*DD + r)*2;
    }
    int flat = g_keepFlat[b*DD + r];
    if (flat < 0) {
        if (lane == 0) {
            if (ob) { ob[0]=0.f; ob[1]=0.f; ob[2]=0.f; ob[3]=0.f; }
            if (os) { os[0]=0.f; os[1]=0.f; }
            if (ol) { ol[0]=0.f; ol[1]=0.f; }
        }
        return;
    }
    size_t co = (size_t)b*NCAND + flat;
    if (lane == 0 && ob) {
        float4 bx = g_candBox[co];
        ob[0] = bx.x; ob[1] = bx.y; ob[2] = bx.z; ob[3] = bx.w;
    }
    if (!os && !ol) return;
    int anchor = g_candIdx[co];
    float va[3]; int ia[3];
#pragma unroll
    for (int s = 0; s < 3; s++) {
        int c = 1 + lane + 32*s;
        if (c <= NC) { va[s] = g_probsT[((size_t)(b*CC + c))*AA + anchor]; ia[s] = c; }
        else         { va[s] = NEGINF; ia[s] = 1 << 20; }
    }
    float f1v = va[0], f2v = NEGINF;
    int   f1i = ia[0], f2i = 1 << 20;
#pragma unroll
    for (int s = 1; s < 3; s++) {
        if (va[s] > f1v)      { f2v = f1v; f2i = f1i; f1v = va[s]; f1i = ia[s]; }
        else if (va[s] > f2v) { f2v = va[s]; f2i = ia[s]; }
    }
    for (int o = 16; o > 0; o >>= 1) {
        float o1v = __shfl_down_sync(0xFFFFFFFFu, f1v, o);
        int   o1i = __shfl_down_sync(0xFFFFFFFFu, f1i, o);
        float o2v = __shfl_down_sync(0xFFFFFFFFu, f2v, o);
        int   o2i = __shfl_down_sync(0xFFFFFFFFu, f2i, o);
        bool a_first = (f1v > o1v) || (f1v == o1v && f1i < o1i);
        float n1v, n2v; int n1i, n2i;
        if (a_first) {
            n1v = f1v; n1i = f1i;
            bool pick = (f2v > o1v) || (f2v == o1v && f2i < o1i);
            n2v = pick ? f2v : o1v; n2i = pick ? f2i : o1i;
        } else {
            n1v = o1v; n1i = o1i;
            bool pick = (o2v > f1v) || (o2v == f1v && o2i < f1i);
            n2v = pick ? o2v : f1v; n2i = pick ? o2i : f1i;
        }
        f1v = n1v; f1i = n1i; f2v = n2v; f2i = n2i;
    }
    if (lane == 0) {
        if (os) { os[0] = f1v; os[1] = f2v; }
        if (ol) { ol[0] = (float)f1i; ol[1] = (float)f2i; }
    }
}

// ---------------- launcher ----------------
extern "C" void kernel_launch(void* const* d_in, const int* in_sizes, int n_in,
                              void* d_out, int out_size) {
    const float* logits  = (const float*)d_in[0];   // (B, A, C)
    const float* rel     = (const float*)d_in[1];   // (B, A, 4)
    const float* anchors = (const float*)d_in[2];   // (A, 4)
    float* out = (float*)d_out;
    int mode = (out_size == BB*DD*8) ? 0 : ((out_size == BB*DD*4) ? 1 : 2);

    dim3 gs((AA + 127)/128, BB);
    softmax_kernel<<<gs, 256>>>(logits, rel, anchors);

    dim3 gt(NC, BB);
    topk_kernel<<<gt, 256>>>();

    classnms_kernel<<<BB*NC, 256>>>();

    (void)cudaFuncSetAttribute(merge_kernel,
                               cudaFuncAttributeMaxDynamicSharedMemorySize,
                               MKEY_N*8);
    merge_kernel<<<BB, 1024, MKEY_N*8>>>();

    output_kernel<<<(BB*DD)/8, 256>>>(out, mode);
}